// round 6
// baseline (speedup 1.0000x reference)
#include <cuda_runtime.h>
#include <math.h>

#define LROWS 128
#define EDIM 768
#define BKC 16
#define NCHUNK 48          // 768/16
#define THREADS 256

__device__ __forceinline__ unsigned long long pk2(float lo, float hi) {
    unsigned long long r;
    asm("mov.b64 %0, {%1, %2};" : "=l"(r) : "f"(lo), "f"(hi));
    return r;
}
__device__ __forceinline__ unsigned long long fma2(unsigned long long a,
                                                   unsigned long long b,
                                                   unsigned long long c) {
    unsigned long long d;
    asm("fma.rn.f32x2 %0, %1, %2, %3;" : "=l"(d) : "l"(a), "l"(b), "l"(c));
    return d;
}
__device__ __forceinline__ float2 up2(unsigned long long v) {
    float lo, hi;
    asm("mov.b64 {%0, %1}, %2;" : "=f"(lo), "=f"(hi) : "l"(v));
    return make_float2(lo, hi);
}

// dynamic smem (floats):
//   uni   [0, 8192)  : phase0/1 w0 staging (7680) | GEMM double buffers (8192) | argmax red (8192)
//   p_c   [8192, +640)
//   p_e   [+640)
//   inv_en[+128)
#define SMEM_FLOATS (8192 + 640 + 640 + 128)

__global__ __launch_bounds__(THREADS, 2)
void som_mlp_kernel(const float* __restrict__ ctx,
                    const float* __restrict__ w0, const float* __restrict__ b0,
                    const float* __restrict__ w1, const float* __restrict__ b1,
                    const float* __restrict__ w2, const float* __restrict__ b2,
                    const float* __restrict__ w3, const float* __restrict__ b3,
                    const float* __restrict__ w4, const float* __restrict__ b4,
                    const float* __restrict__ w5, const float* __restrict__ b5,
                    const float* __restrict__ w6, const float* __restrict__ b6,
                    float* __restrict__ out)
{
    extern __shared__ float sm[];
    float* uni    = sm;
    float* p_c    = sm + 8192;
    float* p_e    = p_c + 640;
    float* inv_en = p_e + 640;

    const int tid  = threadIdx.x;
    const int lane = tid & 31;
    const int wid  = tid >> 5;
    const int p    = blockIdx.x;

    const float* Cb = ctx + (size_t)p * (2 * LROWS * EDIM);
    const float* Eb = Cb + LROWS * EDIM;

    // ---------- phase 0: stage w0 (5 x 1536) into smem ----------
    {
        const float4* src = (const float4*)w0;
        float4*       dst = (float4*)uni;
        for (int f = tid; f < (5 * 2 * EDIM) / 4; f += THREADS) dst[f] = src[f];
    }
    __syncthreads();

    // ---------- phase 1: row norms + first-layer projections ----------
    // Two rows per iteration: one set of w0 LDS serves both rows.
    for (int half = 0; half < 2; ++half) {
        const float* Xb   = half ? Eb : Cb;
        const int    woff = half ? EDIM : 0;
        for (int pr = wid; pr < 64; pr += 8) {
            const float* x0p = Xb + (2 * pr) * EDIM;
            const float* x1p = x0p + EDIM;
            float sq0 = 0.f, sq1 = 0.f;
            float d0[5] = {0,0,0,0,0}, d1[5] = {0,0,0,0,0};
            #pragma unroll
            for (int e = 0; e < EDIM; e += 128) {
                const int o = e + lane * 4;
                float4 x0 = *(const float4*)(x0p + o);
                float4 x1 = *(const float4*)(x1p + o);
                sq0 += x0.x*x0.x + x0.y*x0.y + x0.z*x0.z + x0.w*x0.w;
                sq1 += x1.x*x1.x + x1.y*x1.y + x1.z*x1.z + x1.w*x1.w;
                #pragma unroll
                for (int j = 0; j < 5; ++j) {
                    float4 w = *(const float4*)(uni + j * 1536 + woff + o);
                    d0[j] += x0.x*w.x + x0.y*w.y + x0.z*w.z + x0.w*w.w;
                    d1[j] += x1.x*w.x + x1.y*w.y + x1.z*w.z + x1.w*w.w;
                }
            }
            #pragma unroll
            for (int off = 16; off; off >>= 1) {
                sq0 += __shfl_xor_sync(0xffffffffu, sq0, off);
                sq1 += __shfl_xor_sync(0xffffffffu, sq1, off);
                #pragma unroll
                for (int j = 0; j < 5; ++j) {
                    d0[j] += __shfl_xor_sync(0xffffffffu, d0[j], off);
                    d1[j] += __shfl_xor_sync(0xffffffffu, d1[j], off);
                }
            }
            if (lane == 0) {
                const int r0 = 2 * pr, r1 = 2 * pr + 1;
                float inv0 = rsqrtf(sq0);
                float inv1 = rsqrtf(sq1);
                float* dst = half ? p_e : p_c;
                #pragma unroll
                for (int j = 0; j < 5; ++j) {
                    dst[r0 * 5 + j] = d0[j] * inv0;
                    dst[r1 * 5 + j] = d1[j] * inv1;
                }
                if (half) { inv_en[r0] = inv0; inv_en[r1] = inv1; }
            }
        }
    }
    __syncthreads();

    // ---------- phase 2: 128x128x768 fp32 GEMM (D = C . E^T), FFMA2 ----------
    // Thread (tx,ty): rows {4ty..4ty+3, 64+4ty..+3}, cols {4tx..4tx+3, 64+4tx..+3}
    const int tx = tid & 15;
    const int ty = tid >> 4;

    unsigned long long acc[8][4];
    #pragma unroll
    for (int i = 0; i < 8; ++i)
        #pragma unroll
        for (int j = 0; j < 4; ++j) acc[i][j] = 0ull;

    // global-load lane geometry (fixed per thread)
    const int gr0 = tid >> 2;            // row for fragment 0
    const int gr1 = (tid + 256) >> 2;    // row for fragment 1
    const int gkq = tid & 3;             // k-quad 0..3
    const int sb0 = ((((gr0 >> 2) ^ gkq) << 2) | (gr0 & 3));  // swizzled store base
    const int sb1 = ((((gr1 >> 2) ^ gkq) << 2) | (gr1 & 3));

    float4 rA[2], rB[2];

    // prologue: chunk 0 -> regs -> buf0; then prefetch chunk 1 -> regs
    rA[0] = *(const float4*)(Cb + gr0 * EDIM + gkq * 4);
    rA[1] = *(const float4*)(Cb + gr1 * EDIM + gkq * 4);
    rB[0] = *(const float4*)(Eb + gr0 * EDIM + gkq * 4);
    rB[1] = *(const float4*)(Eb + gr1 * EDIM + gkq * 4);
    {
        float* Ab = uni;
        float* Bb = uni + 2048;
        #pragma unroll
        for (int i = 0; i < 4; ++i) {
            Ab[(gkq * 4 + i) * 128 + sb0] = ((const float*)&rA[0])[i];
            Ab[(gkq * 4 + i) * 128 + sb1] = ((const float*)&rA[1])[i];
            Bb[(gkq * 4 + i) * 128 + sb0] = ((const float*)&rB[0])[i];
            Bb[(gkq * 4 + i) * 128 + sb1] = ((const float*)&rB[1])[i];
        }
    }
    __syncthreads();
    rA[0] = *(const float4*)(Cb + gr0 * EDIM + BKC + gkq * 4);
    rA[1] = *(const float4*)(Cb + gr1 * EDIM + BKC + gkq * 4);
    rB[0] = *(const float4*)(Eb + gr0 * EDIM + BKC + gkq * 4);
    rB[1] = *(const float4*)(Eb + gr1 * EDIM + BKC + gkq * 4);

    for (int kc = 0; kc < NCHUNK; ++kc) {
        // 1) store staged regs (chunk kc+1) into the idle buffer
        if (kc + 1 < NCHUNK) {
            float* Ab = uni + ((kc + 1) & 1) * 4096;
            float* Bb = Ab + 2048;
            #pragma unroll
            for (int i = 0; i < 4; ++i) {
                Ab[(gkq * 4 + i) * 128 + sb0] = ((const float*)&rA[0])[i];
                Ab[(gkq * 4 + i) * 128 + sb1] = ((const float*)&rA[1])[i];
                Bb[(gkq * 4 + i) * 128 + sb0] = ((const float*)&rB[0])[i];
                Bb[(gkq * 4 + i) * 128 + sb1] = ((const float*)&rB[1])[i];
            }
        }
        // 2) kick off global loads for chunk kc+2 (latency spans this chunk's math)
        if (kc + 2 < NCHUNK) {
            const int ko = (kc + 2) * BKC + gkq * 4;
            rA[0] = *(const float4*)(Cb + gr0 * EDIM + ko);
            rA[1] = *(const float4*)(Cb + gr1 * EDIM + ko);
            rB[0] = *(const float4*)(Eb + gr0 * EDIM + ko);
            rB[1] = *(const float4*)(Eb + gr1 * EDIM + ko);
        }
        // 3) compute current chunk
        {
            const float* Ab = uni + (kc & 1) * 4096;
            const float* Bb = Ab + 2048;
            #pragma unroll
            for (int k = 0; k < BKC; ++k) {
                const int kq = k >> 2;
                const int ro = k * 128;
                float4 a0  = *(const float4*)(Ab + ro + ((ty ^ kq) << 2));
                float4 a1  = *(const float4*)(Ab + ro + (((ty + 16) ^ kq) << 2));
                float4 bv0 = *(const float4*)(Bb + ro + ((tx ^ kq) << 2));
                float4 bv1 = *(const float4*)(Bb + ro + (((tx + 16) ^ kq) << 2));
                unsigned long long bb0 = pk2(bv0.x, bv0.y);
                unsigned long long bb1 = pk2(bv0.z, bv0.w);
                unsigned long long bb2 = pk2(bv1.x, bv1.y);
                unsigned long long bb3 = pk2(bv1.z, bv1.w);
                float av[8] = {a0.x, a0.y, a0.z, a0.w, a1.x, a1.y, a1.z, a1.w};
                #pragma unroll
                for (int i = 0; i < 8; ++i) {
                    unsigned long long ad = pk2(av[i], av[i]);
                    acc[i][0] = fma2(ad, bb0, acc[i][0]);
                    acc[i][1] = fma2(ad, bb1, acc[i][1]);
                    acc[i][2] = fma2(ad, bb2, acc[i][2]);
                    acc[i][3] = fma2(ad, bb3, acc[i][3]);
                }
            }
        }
        __syncthreads();
    }

    // ---------- phase 3: scaled argmax over columns ----------
    // Two slots per thread/row: slot tx covers cols [4tx,4tx+3] (lo half),
    // slot 16+tx covers cols [64+4tx, 64+4tx+3] (hi half). Logical slot order
    // 0..31 is strictly ascending in column index -> preserves argmax tie-break.
    float2* red = (float2*)uni;   // [128][32] float2
    #pragma unroll
    for (int i = 0; i < 8; ++i) {
        const int row = (i < 4) ? (ty * 4 + i) : (64 + ty * 4 + (i - 4));
        float bl = -3.402823466e38f; int il = 0;
        float bh = -3.402823466e38f; int ih = 0;
        #pragma unroll
        for (int jp = 0; jp < 2; ++jp) {
            float2 v = up2(acc[i][jp]);
            int c0 = 4 * tx + jp * 2;
            float s0 = v.x * inv_en[c0];
            float s1 = v.y * inv_en[c0 + 1];
            if (s0 > bl) { bl = s0; il = c0; }
            if (s1 > bl) { bl = s1; il = c0 + 1; }
        }
        #pragma unroll
        for (int jp = 2; jp < 4; ++jp) {
            float2 v = up2(acc[i][jp]);
            int c0 = 64 + 4 * tx + (jp - 2) * 2;
            float s0 = v.x * inv_en[c0];
            float s1 = v.y * inv_en[c0 + 1];
            if (s0 > bh) { bh = s0; ih = c0; }
            if (s1 > bh) { bh = s1; ih = c0 + 1; }
        }
        red[row * 32 + ((tx + row) & 31)]        = make_float2(bl, __int_as_float(il));
        red[row * 32 + (((16 + tx) + row) & 31)] = make_float2(bh, __int_as_float(ih));
    }
    __syncthreads();

    // ---------- phase 4: per-row MLP + block sum ----------
    float partial = 0.f;
    if (tid < 128) {
        const int l = tid;
        float best = -3.402823466e38f;
        int   bidx = 0;
        #pragma unroll
        for (int t = 0; t < 32; ++t) {   // ascending logical slot = ascending cols
            float2 v = red[l * 32 + ((t + l) & 31)];
            if (v.x > best) { best = v.x; bidx = __float_as_int(v.y); }
        }
        float h0[5];
        #pragma unroll
        for (int j = 0; j < 5; ++j)
            h0[j] = tanhf(p_c[l * 5 + j] + p_e[bidx * 5 + j] + __ldg(b0 + j));
        float s0 = __ldg(b1 + 0), s1 = __ldg(b1 + 1);
        #pragma unroll
        for (int j = 0; j < 5; ++j) {
            s0 += __ldg(w1 + j)     * h0[j];
            s1 += __ldg(w1 + 5 + j) * h0[j];
        }
        float h10 = tanhf(s0), h11 = tanhf(s1);
        float z = tanhf(__ldg(w2) * h10 + __ldg(w2 + 1) * h11 + __ldg(b2));
        z = tanhf(__ldg(w3) * z + __ldg(b3));
        z = tanhf(__ldg(w4) * z + __ldg(b4));
        z = tanhf(__ldg(w5) * z + __ldg(b5));
        partial = __ldg(w6) * z + __ldg(b6);
    }
    #pragma unroll
    for (int off = 16; off; off >>= 1)
        partial += __shfl_xor_sync(0xffffffffu, partial, off);
    __shared__ float ssum[8];
    if (lane == 0) ssum[wid] = partial;
    __syncthreads();
    if (tid == 0) {
        float t = 0.f;
        #pragma unroll
        for (int w = 0; w < 8; ++w) t += ssum[w];
        out[p] = t;
    }
}

extern "C" void kernel_launch(void* const* d_in, const int* in_sizes, int n_in,
                              void* d_out, int out_size)
{
    const float* ctx = (const float*)d_in[0];
    const float* w0 = (const float*)d_in[1];  const float* b0 = (const float*)d_in[2];
    const float* w1 = (const float*)d_in[3];  const float* b1 = (const float*)d_in[4];
    const float* w2 = (const float*)d_in[5];  const float* b2 = (const float*)d_in[6];
    const float* w3 = (const float*)d_in[7];  const float* b3 = (const float*)d_in[8];
    const float* w4 = (const float*)d_in[9];  const float* b4 = (const float*)d_in[10];
    const float* w5 = (const float*)d_in[11]; const float* b5 = (const float*)d_in[12];
    const float* w6 = (const float*)d_in[13]; const float* b6 = (const float*)d_in[14];
    float* out = (float*)d_out;

    const int smem_bytes = SMEM_FLOATS * 4;   // 38400
    cudaFuncSetAttribute(som_mlp_kernel,
                         cudaFuncAttributeMaxDynamicSharedMemorySize, smem_bytes);
    som_mlp_kernel<<<1024, THREADS, smem_bytes>>>(
        ctx, w0, b0, w1, b1, w2, b2, w3, b3, w4, b4, w5, b5, w6, b6, out);
}

// round 10
// speedup vs baseline: 1.9772x; 1.9772x over previous
#include <cuda_runtime.h>
#include <math.h>

#define THREADS 256
#define NCH 12            // 768 / 64
#define EDIM 768

// ---- smem byte offsets ----
#define A_HI 0            // 128 x 64 bf16, 128B rows, SW128 = 16KB
#define A_LO 16384
#define B_HI 32768
#define B_LO 49152
#define WC_HI 65536       // 8 x 64 bf16 = 1KB (rows 5..7 zero)
#define WC_LO 66560
#define WE_HI 67584
#define WE_LO 68608
#define O_ICN 69632       // inv|c| [128] floats
#define O_IEN 70144       // inv|e| [128]
#define O_SSUM 70656
#define SMEM_BYTES 70720
// aliases (used after GEMM only)
#define O_RED 0           // float2[128][8] = 8KB
#define O_PCS 16384       // float[128][8]
#define O_PES 32768       // float[128][8]

static __device__ __forceinline__ unsigned smem_u32(const void* p) {
    unsigned a;
    asm("{ .reg .u64 t; cvta.to.shared.u64 t, %1; cvt.u32.u64 %0, t; }" : "=r"(a) : "l"(p));
    return a;
}
static __device__ __forceinline__ unsigned sw128(unsigned o) { return o ^ ((o >> 3) & 0x70u); }

static __device__ __forceinline__ void ldsm4(unsigned& r0, unsigned& r1, unsigned& r2, unsigned& r3,
                                             unsigned a) {
    asm volatile("ldmatrix.sync.aligned.m8n8.x4.shared.b16 {%0,%1,%2,%3}, [%4];"
                 : "=r"(r0), "=r"(r1), "=r"(r2), "=r"(r3) : "r"(a));
}
static __device__ __forceinline__ void ldsm2(unsigned& r0, unsigned& r1, unsigned a) {
    asm volatile("ldmatrix.sync.aligned.m8n8.x2.shared.b16 {%0,%1}, [%2];"
                 : "=r"(r0), "=r"(r1) : "r"(a));
}
static __device__ __forceinline__ void mma16816(float* c, const unsigned* a, const unsigned* b) {
    asm volatile("mma.sync.aligned.m16n8k16.row.col.f32.bf16.bf16.f32 "
                 "{%0,%1,%2,%3}, {%4,%5,%6,%7}, {%8,%9}, {%0,%1,%2,%3};"
                 : "+f"(c[0]), "+f"(c[1]), "+f"(c[2]), "+f"(c[3])
                 : "r"(a[0]), "r"(a[1]), "r"(a[2]), "r"(a[3]), "r"(b[0]), "r"(b[1]));
}
// A-operand (m16k16 row-major) ldmatrix address for this lane (tile-relative)
static __device__ __forceinline__ unsigned asw(int row0, int kb, int lane) {
    const int m = lane >> 3, r = lane & 7;
    const int row = row0 + ((m & 1) << 3) + r;
    const int byte = kb + ((m >> 1) << 4);
    return (unsigned)(row * 128) + (unsigned)(byte ^ ((row & 7) << 4));
}
// B-operand pair (two n8k16 tiles) ldmatrix address
static __device__ __forceinline__ unsigned bsw(int n0, int kb, int lane) {
    const int m = lane >> 3, r = lane & 7;
    const int row = n0 + ((m >> 1) << 3) + r;
    const int byte = kb + ((m & 1) << 4);
    return (unsigned)(row * 128) + (unsigned)(byte ^ ((row & 7) << 4));
}
// fp32x4 -> hi bf16x4 + residual-lo bf16x4, accumulate sum of squares
static __device__ __forceinline__ void cvt_store(char* hip, char* lop, float4 v, float& sq) {
    sq += v.x * v.x + v.y * v.y + v.z * v.z + v.w * v.w;
    unsigned h01, h23, l01, l23;
    asm("cvt.rn.bf16x2.f32 %0, %2, %1;" : "=r"(h01) : "f"(v.x), "f"(v.y));
    asm("cvt.rn.bf16x2.f32 %0, %2, %1;" : "=r"(h23) : "f"(v.z), "f"(v.w));
    float f0 = __uint_as_float(h01 << 16);
    float f1 = __uint_as_float(h01 & 0xffff0000u);
    float f2 = __uint_as_float(h23 << 16);
    float f3 = __uint_as_float(h23 & 0xffff0000u);
    float r0 = v.x - f0, r1 = v.y - f1, r2 = v.z - f2, r3 = v.w - f3;
    asm("cvt.rn.bf16x2.f32 %0, %2, %1;" : "=r"(l01) : "f"(r0), "f"(r1));
    asm("cvt.rn.bf16x2.f32 %0, %2, %1;" : "=r"(l23) : "f"(r2), "f"(r3));
    *(uint2*)hip = make_uint2(h01, h23);
    *(uint2*)lop = make_uint2(l01, l23);
}

__global__ __launch_bounds__(THREADS, 2)
void som_mma_kernel(const float* __restrict__ ctx,
                    const float* __restrict__ w0, const float* __restrict__ b0,
                    const float* __restrict__ w1, const float* __restrict__ b1,
                    const float* __restrict__ w2, const float* __restrict__ b2,
                    const float* __restrict__ w3, const float* __restrict__ b3,
                    const float* __restrict__ w4, const float* __restrict__ b4,
                    const float* __restrict__ w5, const float* __restrict__ b5,
                    const float* __restrict__ w6, const float* __restrict__ b6,
                    float* __restrict__ out)
{
    extern __shared__ char smem[];
    const unsigned sb = smem_u32(smem);
    float* icn  = (float*)(smem + O_ICN);
    float* ien  = (float*)(smem + O_IEN);
    float* ssum = (float*)(smem + O_SSUM);

    const int tid  = threadIdx.x;
    const int lane = tid & 31;
    const int wid  = tid >> 5;
    const int p    = blockIdx.x;

    const float* Cb = ctx + (size_t)p * (2 * 128 * EDIM);
    const float* Eb = Cb + 128 * EDIM;

    // zero the 4KB w0 tile region once (pad rows 5..7 stay zero forever)
    *(uint4*)(smem + WC_HI + tid * 16) = make_uint4(0u, 0u, 0u, 0u);

    // conversion geometry: 8 threads per row, rows tr+32i, quads tq / tq+8
    const int tr = tid >> 3, tq = tid & 7;
    // compute geometry: warp (mw, nw) owns rows mrow..+31, cols ncol..+63
    const int mw = wid & 3, nw = wid >> 2;
    const int mrow = mw * 32, ncol = nw * 64;
    const int g = lane >> 2, t = lane & 3;

    float accD[2][8][4];
    float accP[2][4];
    #pragma unroll
    for (int mt = 0; mt < 2; ++mt) {
        #pragma unroll
        for (int nt = 0; nt < 8; ++nt)
            #pragma unroll
            for (int k = 0; k < 4; ++k) accD[mt][nt][k] = 0.f;
        #pragma unroll
        for (int k = 0; k < 4; ++k) accP[mt][k] = 0.f;
    }
    float sqC[4] = {0.f, 0.f, 0.f, 0.f};
    float sqE[4] = {0.f, 0.f, 0.f, 0.f};

    __syncthreads();

    for (int c = 0; c < NCH; ++c) {
        const int cb = c * 64;
        if (c) __syncthreads();          // previous chunk's reads complete

        // ---- stage chunk: fp32 -> bf16 hi/lo, accumulate norms ----
        #pragma unroll
        for (int i = 0; i < 4; ++i) {
            const int row = tr + 32 * i;
            const float* cp = Cb + row * EDIM + cb;
            const float* ep = Eb + row * EDIM + cb;
            float4 c0 = *(const float4*)(cp + tq * 4);
            float4 c1 = *(const float4*)(cp + (tq + 8) * 4);
            float4 e0 = *(const float4*)(ep + tq * 4);
            float4 e1 = *(const float4*)(ep + (tq + 8) * 4);
            const unsigned o0 = sw128((unsigned)(row * 128 + tq * 8));
            const unsigned o1 = sw128((unsigned)(row * 128 + 64 + tq * 8));
            cvt_store(smem + A_HI + o0, smem + A_LO + o0, c0, sqC[i]);
            cvt_store(smem + A_HI + o1, smem + A_LO + o1, c1, sqC[i]);
            cvt_store(smem + B_HI + o0, smem + B_LO + o0, e0, sqE[i]);
            cvt_store(smem + B_HI + o1, smem + B_LO + o1, e1, sqE[i]);
        }
        if (tid < 160) {   // w0 chunk: 5 rows x 64 floats x {c,e}
            const int half = tid / 80, rem = tid % 80;
            const int r = rem >> 4, q = rem & 15;
            float4 wv = *(const float4*)(w0 + r * 1536 + half * 768 + cb + q * 4);
            float dmy = 0.f;
            const unsigned o = sw128((unsigned)(r * 128 + q * 8));
            char* hb = smem + (half ? WE_HI : WC_HI);
            cvt_store(hb + o, hb + 1024 + o, wv, dmy);
        }
        __syncthreads();

        // ---- main GEMM: 3-split bf16, 4 k16 steps ----
        #pragma unroll
        for (int s = 0; s < 4; ++s) {
            const int kb = s * 32;
            unsigned Ah[8], Ax[8], Bf[16];
            ldsm4(Ah[0], Ah[1], Ah[2], Ah[3], sb + A_HI + asw(mrow, kb, lane));
            ldsm4(Ah[4], Ah[5], Ah[6], Ah[7], sb + A_HI + asw(mrow + 16, kb, lane));
            #pragma unroll
            for (int pq = 0; pq < 4; ++pq)
                ldsm4(Bf[4*pq], Bf[4*pq+1], Bf[4*pq+2], Bf[4*pq+3],
                      sb + B_HI + bsw(ncol + 16 * pq, kb, lane));
            #pragma unroll
            for (int mt = 0; mt < 2; ++mt)
                #pragma unroll
                for (int nt = 0; nt < 8; ++nt)
                    mma16816(accD[mt][nt], Ah + 4 * mt, Bf + (nt >> 1) * 4 + (nt & 1) * 2);
            // lo(A) * hi(B)
            ldsm4(Ax[0], Ax[1], Ax[2], Ax[3], sb + A_LO + asw(mrow, kb, lane));
            ldsm4(Ax[4], Ax[5], Ax[6], Ax[7], sb + A_LO + asw(mrow + 16, kb, lane));
            #pragma unroll
            for (int mt = 0; mt < 2; ++mt)
                #pragma unroll
                for (int nt = 0; nt < 8; ++nt)
                    mma16816(accD[mt][nt], Ax + 4 * mt, Bf + (nt >> 1) * 4 + (nt & 1) * 2);
            // hi(A) * lo(B)
            #pragma unroll
            for (int pq = 0; pq < 4; ++pq)
                ldsm4(Bf[4*pq], Bf[4*pq+1], Bf[4*pq+2], Bf[4*pq+3],
                      sb + B_LO + bsw(ncol + 16 * pq, kb, lane));
            #pragma unroll
            for (int mt = 0; mt < 2; ++mt)
                #pragma unroll
                for (int nt = 0; nt < 8; ++nt)
                    mma16816(accD[mt][nt], Ah + 4 * mt, Bf + (nt >> 1) * 4 + (nt & 1) * 2);
        }

        // ---- w0 projection GEMM (warps 0-3: p_c from A tiles; 4-7: p_e from B tiles) ----
        {
            const unsigned phi = (wid < 4) ? (sb + A_HI) : (sb + B_HI);
            const unsigned plo = phi + 16384;
            const unsigned whi = (wid < 4) ? (sb + WC_HI) : (sb + WE_HI);
            const unsigned wlo = whi + 1024;
            #pragma unroll
            for (int s = 0; s < 4; ++s) {
                const int kb = s * 32;
                unsigned Ph[8], Pl[8], W[4];
                ldsm4(Ph[0], Ph[1], Ph[2], Ph[3], phi + asw(mrow, kb, lane));
                ldsm4(Ph[4], Ph[5], Ph[6], Ph[7], phi + asw(mrow + 16, kb, lane));
                ldsm4(Pl[0], Pl[1], Pl[2], Pl[3], plo + asw(mrow, kb, lane));
                ldsm4(Pl[4], Pl[5], Pl[6], Pl[7], plo + asw(mrow + 16, kb, lane));
                ldsm2(W[0], W[1], whi + bsw(0, kb, lane & 15));
                ldsm2(W[2], W[3], wlo + bsw(0, kb, lane & 15));
                mma16816(accP[0], Ph,     W);      // hi*hi
                mma16816(accP[1], Ph + 4, W);
                mma16816(accP[0], Pl,     W);      // lo*hi
                mma16816(accP[1], Pl + 4, W);
                mma16816(accP[0], Ph,     W + 2);  // hi*lo
                mma16816(accP[1], Ph + 4, W + 2);
            }
        }
    }

    // ---- norm reduction over the 8-lane row groups ----
    #pragma unroll
    for (int i = 0; i < 4; ++i) {
        float a = sqC[i], b = sqE[i];
        #pragma unroll
        for (int off = 1; off < 8; off <<= 1) {
            a += __shfl_xor_sync(0xffffffffu, a, off);
            b += __shfl_xor_sync(0xffffffffu, b, off);
        }
        if (tq == 0) {
            const int row = tr + 32 * i;
            icn[row] = rsqrtf(a);
            ien[row] = rsqrtf(b);
        }
    }
    __syncthreads();   // all tile reads done; norms visible; aliasing now safe

    // ---- argmax: (value, lower-index-wins) == first-occurrence semantics ----
    float iev[16];
    #pragma unroll
    for (int nt = 0; nt < 8; ++nt) {
        iev[nt*2]     = ien[ncol + nt * 8 + 2 * t];
        iev[nt*2 + 1] = ien[ncol + nt * 8 + 2 * t + 1];
    }
    float2* red = (float2*)(smem + O_RED);
    const int slot = nw * 4 + t;
    #pragma unroll
    for (int h = 0; h < 4; ++h) {
        const int mt = h >> 1, up = h & 1;
        const int row = mrow + mt * 16 + up * 8 + g;
        float best = -3.402823466e38f;
        int   bi = 1 << 30;
        #pragma unroll
        for (int nt = 0; nt < 8; ++nt) {
            const float v0 = accD[mt][nt][up * 2]     * iev[nt*2];
            const float v1 = accD[mt][nt][up * 2 + 1] * iev[nt*2 + 1];
            const int c0 = ncol + nt * 8 + 2 * t;
            if (v0 > best || (v0 == best && c0 < bi)) { best = v0; bi = c0; }
            if (v1 > best || (v1 == best && c0 + 1 < bi)) { best = v1; bi = c0 + 1; }
        }
        red[row * 8 + slot] = make_float2(best, __int_as_float(bi));
    }

    // ---- write scaled p_c / p_e ----
    {
        float* dst = (wid < 4) ? (float*)(smem + O_PCS) : (float*)(smem + O_PES);
        const float* inv = (wid < 4) ? icn : ien;
        const int j0 = 2 * t, j1 = 2 * t + 1;
        #pragma unroll
        for (int mt = 0; mt < 2; ++mt) {
            const int r0 = mrow + mt * 16 + g, r1 = r0 + 8;
            if (j0 < 5) {
                dst[r0 * 8 + j0] = accP[mt][0] * inv[r0];
                dst[r1 * 8 + j0] = accP[mt][2] * inv[r1];
            }
            if (j1 < 5) {
                dst[r0 * 8 + j1] = accP[mt][1] * inv[r0];
                dst[r1 * 8 + j1] = accP[mt][3] * inv[r1];
            }
        }
    }
    __syncthreads();

    // ---- per-row MLP + block sum ----
    const float* pcs = (const float*)(smem + O_PCS);
    const float* pes = (const float*)(smem + O_PES);
    float partial = 0.f;
    if (tid < 128) {
        const int l = tid;
        float best = -3.402823466e38f;
        int   bi = 1 << 30;
        #pragma unroll
        for (int s2 = 0; s2 < 8; ++s2) {
            const float2 v = red[l * 8 + s2];
            const int cc = __float_as_int(v.y);
            if (v.x > best || (v.x == best && cc < bi)) { best = v.x; bi = cc; }
        }
        float h0[5];
        #pragma unroll
        for (int j = 0; j < 5; ++j)
            h0[j] = tanhf(pcs[l * 8 + j] + pes[bi * 8 + j] + __ldg(b0 + j));
        float s0 = __ldg(b1 + 0), s1 = __ldg(b1 + 1);
        #pragma unroll
        for (int j = 0; j < 5; ++j) {
            s0 += __ldg(w1 + j)     * h0[j];
            s1 += __ldg(w1 + 5 + j) * h0[j];
        }
        float h10 = tanhf(s0), h11 = tanhf(s1);
        float z = tanhf(__ldg(w2) * h10 + __ldg(w2 + 1) * h11 + __ldg(b2));
        z = tanhf(__ldg(w3) * z + __ldg(b3));
        z = tanhf(__ldg(w4) * z + __ldg(b4));
        z = tanhf(__ldg(w5) * z + __ldg(b5));
        partial = __ldg(w6) * z + __ldg(b6);
    }
    #pragma unroll
    for (int off = 16; off; off >>= 1)
        partial += __shfl_xor_sync(0xffffffffu, partial, off);
    if (lane == 0) ssum[wid] = partial;
    __syncthreads();
    if (tid == 0) {
        float tot = 0.f;
        #pragma unroll
        for (int w = 0; w < 8; ++w) tot += ssum[w];
        out[p] = tot;
    }
}

extern "C" void kernel_launch(void* const* d_in, const int* in_sizes, int n_in,
                              void* d_out, int out_size)
{
    const float* ctx = (const float*)d_in[0];
    const float* w0 = (const float*)d_in[1];  const float* b0 = (const float*)d_in[2];
    const float* w1 = (const float*)d_in[3];  const float* b1 = (const float*)d_in[4];
    const float* w2 = (const float*)d_in[5];  const float* b2 = (const float*)d_in[6];
    const float* w3 = (const float*)d_in[7];  const float* b3 = (const float*)d_in[8];
    const float* w4 = (const float*)d_in[9];  const float* b4 = (const float*)d_in[10];
    const float* w5 = (const float*)d_in[11]; const float* b5 = (const float*)d_in[12];
    const float* w6 = (const float*)d_in[13]; const float* b6 = (const float*)d_in[14];
    float* out = (float*)d_out;

    cudaFuncSetAttribute(som_mma_kernel,
                         cudaFuncAttributeMaxDynamicSharedMemorySize, SMEM_BYTES);
    som_mma_kernel<<<1024, THREADS, SMEM_BYTES>>>(
        ctx, w0, b0, w1, b1, w2, b2, w3, b3, w4, b4, w5, b5, w6, b6, out);
}

// round 12
// speedup vs baseline: 3.7045x; 1.8736x over previous
#include <cuda_runtime.h>
#include <math.h>

#define THREADS 256
#define NCH 24            // 768 / 32
#define EDIM 768

// ---- smem byte offsets ----
#define ST_C 0            // fp32 staging C: 128 rows x 128B = 16KB
#define ST_E 16384        // fp32 staging E: 16KB
#define ST_W 32768        // fp32 staging w0: 10 rows x 128B = 1280B (pad to 2KB)
#define A_HI 34816        // 128 x 32 bf16, 64B rows, SW64 = 8KB
#define A_LO 43008
#define B_HI 51200
#define B_LO 59392
#define WC_HI 67584       // 8 x 32 bf16 = 512B (rows 5..7 zero)
#define WC_LO 68096
#define WE_HI 68608
#define WE_LO 69120
#define O_ICN 69632       // inv|c| [128] floats
#define O_IEN 70144       // inv|e| [128]
#define O_SSUM 70656
#define SMEM_BYTES 70720
// aliases (used after GEMM only; all tile/staging reads complete by then)
#define O_RED 0           // float2[128][8] = 8KB
#define O_PCS 16384       // float[128][8]
#define O_PES 24576       // float[128][8]

#define SW64(o) ((o) ^ (((o) >> 3) & 0x30u))

static __device__ __forceinline__ unsigned smem_u32(const void* p) {
    unsigned a;
    asm("{ .reg .u64 t; cvta.to.shared.u64 t, %1; cvt.u32.u64 %0, t; }" : "=r"(a) : "l"(p));
    return a;
}
static __device__ __forceinline__ void cp16(unsigned dst, const void* src) {
    asm volatile("cp.async.cg.shared.global [%0], [%1], 16;" :: "r"(dst), "l"(src));
}
static __device__ __forceinline__ void cp_commit() {
    asm volatile("cp.async.commit_group;" ::: "memory");
}
static __device__ __forceinline__ void cp_wait0() {
    asm volatile("cp.async.wait_group 0;" ::: "memory");
}
static __device__ __forceinline__ void ldsm4(unsigned& r0, unsigned& r1, unsigned& r2, unsigned& r3,
                                             unsigned a) {
    asm volatile("ldmatrix.sync.aligned.m8n8.x4.shared.b16 {%0,%1,%2,%3}, [%4];"
                 : "=r"(r0), "=r"(r1), "=r"(r2), "=r"(r3) : "r"(a));
}
static __device__ __forceinline__ void ldsm2(unsigned& r0, unsigned& r1, unsigned a) {
    asm volatile("ldmatrix.sync.aligned.m8n8.x2.shared.b16 {%0,%1}, [%2];"
                 : "=r"(r0), "=r"(r1) : "r"(a));
}
static __device__ __forceinline__ void mma16816(float* c, const unsigned* a, const unsigned* b) {
    asm volatile("mma.sync.aligned.m16n8k16.row.col.f32.bf16.bf16.f32 "
                 "{%0,%1,%2,%3}, {%4,%5,%6,%7}, {%8,%9}, {%0,%1,%2,%3};"
                 : "+f"(c[0]), "+f"(c[1]), "+f"(c[2]), "+f"(c[3])
                 : "r"(a[0]), "r"(a[1]), "r"(a[2]), "r"(a[3]), "r"(b[0]), "r"(b[1]));
}
// A-operand (m16k16 row-major) ldmatrix address, 64B rows, SW64
static __device__ __forceinline__ unsigned asw(int row0, int kb, int lane) {
    const int m = lane >> 3, r = lane & 7;
    const int row = row0 + ((m & 1) << 3) + r;
    const int byte = kb + ((m >> 1) << 4);
    return SW64((unsigned)(row * 64 + byte));
}
// B-operand (two n8k16 tiles for ldsm4 / one for ldsm2) address
static __device__ __forceinline__ unsigned bsw(int n0, int kb, int lane) {
    const int m = lane >> 3, r = lane & 7;
    const int row = n0 + ((m >> 1) << 3) + r;
    const int byte = kb + ((m & 1) << 4);
    return SW64((unsigned)(row * 64 + byte));
}
// fp32x4 -> hi bf16x4 + residual-lo bf16x4, accumulate sum of squares
static __device__ __forceinline__ void cvt_store(char* hip, char* lop, float4 v, float& sq) {
    sq += v.x * v.x + v.y * v.y + v.z * v.z + v.w * v.w;
    unsigned h01, h23, l01, l23;
    asm("cvt.rn.bf16x2.f32 %0, %2, %1;" : "=r"(h01) : "f"(v.x), "f"(v.y));
    asm("cvt.rn.bf16x2.f32 %0, %2, %1;" : "=r"(h23) : "f"(v.z), "f"(v.w));
    float f0 = __uint_as_float(h01 << 16);
    float f1 = __uint_as_float(h01 & 0xffff0000u);
    float f2 = __uint_as_float(h23 << 16);
    float f3 = __uint_as_float(h23 & 0xffff0000u);
    float r0 = v.x - f0, r1 = v.y - f1, r2 = v.z - f2, r3 = v.w - f3;
    asm("cvt.rn.bf16x2.f32 %0, %2, %1;" : "=r"(l01) : "f"(r0), "f"(r1));
    asm("cvt.rn.bf16x2.f32 %0, %2, %1;" : "=r"(l23) : "f"(r2), "f"(r3));
    *(uint2*)hip = make_uint2(h01, h23);
    *(uint2*)lop = make_uint2(l01, l23);
}

__global__ __launch_bounds__(THREADS, 2)
void som_mma_kernel(const float* __restrict__ ctx,
                    const float* __restrict__ w0, const float* __restrict__ b0,
                    const float* __restrict__ w1, const float* __restrict__ b1,
                    const float* __restrict__ w2, const float* __restrict__ b2,
                    const float* __restrict__ w3, const float* __restrict__ b3,
                    const float* __restrict__ w4, const float* __restrict__ b4,
                    const float* __restrict__ w5, const float* __restrict__ b5,
                    const float* __restrict__ w6, const float* __restrict__ b6,
                    float* __restrict__ out)
{
    extern __shared__ char smem[];
    const unsigned sb = smem_u32(smem);
    float* icn  = (float*)(smem + O_ICN);
    float* ien  = (float*)(smem + O_IEN);
    float* ssum = (float*)(smem + O_SSUM);

    const int tid  = threadIdx.x;
    const int lane = tid & 31;
    const int wid  = tid >> 5;
    const int p    = blockIdx.x;

    const float* Cb = ctx + (size_t)p * (2 * 128 * EDIM);
    const float* Eb = Cb + 128 * EDIM;

    // zero w0 tile pads (rows 5..7 of each of the 4 tiles stay zero)
    if (tid < 128) *(uint4*)(smem + WC_HI + tid * 16) = make_uint4(0u, 0u, 0u, 0u);

    // conversion geometry: 8 threads/row, quad rotation kills LDS conflicts
    const int cr = tid >> 3, cq = tid & 7;
    // compute geometry: warp (mw, nw) owns rows mrow..+31, cols ncol..+63
    const int mw = wid & 3, nw = wid >> 2;
    const int mrow = mw * 32, ncol = nw * 64;
    const int g = lane >> 2, t = lane & 3;

    float accD[2][8][4];
    float accP[2][4];
    #pragma unroll
    for (int mt = 0; mt < 2; ++mt) {
        #pragma unroll
        for (int nt = 0; nt < 8; ++nt)
            #pragma unroll
            for (int k = 0; k < 4; ++k) accD[mt][nt][k] = 0.f;
        #pragma unroll
        for (int k = 0; k < 4; ++k) accP[mt][k] = 0.f;
    }
    float sqC[4] = {0.f, 0.f, 0.f, 0.f};
    float sqE[4] = {0.f, 0.f, 0.f, 0.f};

    // ---- prologue: async-stage chunk 0 ----
    {
        #pragma unroll
        for (int j = 0; j < 4; ++j) {
            const int o = tid + 256 * j;                 // 0..1023
            const int row = o >> 3, q = o & 7;
            cp16(sb + ST_C + o * 16, Cb + row * EDIM + q * 4);
            cp16(sb + ST_E + o * 16, Eb + row * EDIM + q * 4);
        }
        if (tid < 80) {
            const int r = tid >> 3, q = tid & 7;         // r: 0..9 (5 c-rows, 5 e-rows)
            cp16(sb + ST_W + tid * 16, w0 + (r % 5) * 1536 + (r / 5) * 768 + q * 4);
        }
        cp_commit();
    }
    __syncthreads();   // covers the w0-pad zeroing

    for (int c = 0; c < NCH; ++c) {
        cp_wait0();
        __syncthreads();   // staging[c] visible to all; GEMM c-1 tile reads done

        // ---- convert: LDS staging -> bf16 hi/lo tiles, accumulate norms ----
        #pragma unroll
        for (int i = 0; i < 4; ++i) {
            const int row = cr + 32 * i;
            const int qq = (cq + row) & 7;
            float4 cv = *(const float4*)(smem + ST_C + row * 128 + qq * 16);
            float4 ev = *(const float4*)(smem + ST_E + row * 128 + qq * 16);
            const unsigned o = SW64((unsigned)(row * 64 + qq * 8));
            cvt_store(smem + A_HI + o, smem + A_LO + o, cv, sqC[i]);
            cvt_store(smem + B_HI + o, smem + B_LO + o, ev, sqE[i]);
        }
        if (tid < 80) {
            const int r = tid >> 3, q = tid & 7;
            float4 wv = *(const float4*)(smem + ST_W + tid * 16);
            const int half = r / 5, rr = r % 5;
            char* hb = smem + (half ? WE_HI : WC_HI);
            float dmy = 0.f;
            const unsigned o = SW64((unsigned)(rr * 64 + q * 8));
            cvt_store(hb + o, hb + 512 + o, wv, dmy);
        }
        __syncthreads();   // tiles ready; staging free for chunk c+1

        // ---- issue async stage of chunk c+1 (overlaps the GEMM below) ----
        if (c + 1 < NCH) {
            const int cb = (c + 1) * 32;
            #pragma unroll
            for (int j = 0; j < 4; ++j) {
                const int o = tid + 256 * j;
                const int row = o >> 3, q = o & 7;
                cp16(sb + ST_C + o * 16, Cb + row * EDIM + cb + q * 4);
                cp16(sb + ST_E + o * 16, Eb + row * EDIM + cb + q * 4);
            }
            if (tid < 80) {
                const int r = tid >> 3, q = tid & 7;
                cp16(sb + ST_W + tid * 16, w0 + (r % 5) * 1536 + (r / 5) * 768 + cb + q * 4);
            }
            cp_commit();
        }

        // ---- main GEMM: 3-split bf16, 2 k16 steps ----
        #pragma unroll
        for (int s = 0; s < 2; ++s) {
            const int kb = s * 32;
            unsigned Ah[8], Ax[8], Bf[16];
            ldsm4(Ah[0], Ah[1], Ah[2], Ah[3], sb + A_HI + asw(mrow, kb, lane));
            ldsm4(Ah[4], Ah[5], Ah[6], Ah[7], sb + A_HI + asw(mrow + 16, kb, lane));
            #pragma unroll
            for (int pq = 0; pq < 4; ++pq)
                ldsm4(Bf[4*pq], Bf[4*pq+1], Bf[4*pq+2], Bf[4*pq+3],
                      sb + B_HI + bsw(ncol + 16 * pq, kb, lane));
            #pragma unroll
            for (int mt = 0; mt < 2; ++mt)
                #pragma unroll
                for (int nt = 0; nt < 8; ++nt)
                    mma16816(accD[mt][nt], Ah + 4 * mt, Bf + (nt >> 1) * 4 + (nt & 1) * 2);
            ldsm4(Ax[0], Ax[1], Ax[2], Ax[3], sb + A_LO + asw(mrow, kb, lane));
            ldsm4(Ax[4], Ax[5], Ax[6], Ax[7], sb + A_LO + asw(mrow + 16, kb, lane));
            #pragma unroll
            for (int mt = 0; mt < 2; ++mt)
                #pragma unroll
                for (int nt = 0; nt < 8; ++nt)
                    mma16816(accD[mt][nt], Ax + 4 * mt, Bf + (nt >> 1) * 4 + (nt & 1) * 2);
            #pragma unroll
            for (int pq = 0; pq < 4; ++pq)
                ldsm4(Bf[4*pq], Bf[4*pq+1], Bf[4*pq+2], Bf[4*pq+3],
                      sb + B_LO + bsw(ncol + 16 * pq, kb, lane));
            #pragma unroll
            for (int mt = 0; mt < 2; ++mt)
                #pragma unroll
                for (int nt = 0; nt < 8; ++nt)
                    mma16816(accD[mt][nt], Ah + 4 * mt, Bf + (nt >> 1) * 4 + (nt & 1) * 2);
        }

        // ---- w0 projection (warps 0-3: p_c from A tiles; 4-7: p_e from B tiles) ----
        {
            const unsigned phi = (wid < 4) ? (sb + A_HI) : (sb + B_HI);
            const unsigned plo = phi + 8192;
            const unsigned whi = (wid < 4) ? (sb + WC_HI) : (sb + WE_HI);
            const unsigned wlo = whi + 512;
            #pragma unroll
            for (int s = 0; s < 2; ++s) {
                const int kb = s * 32;
                unsigned Ph[8], Pl[8], W[4];
                ldsm4(Ph[0], Ph[1], Ph[2], Ph[3], phi + asw(mrow, kb, lane));
                ldsm4(Ph[4], Ph[5], Ph[6], Ph[7], phi + asw(mrow + 16, kb, lane));
                ldsm4(Pl[0], Pl[1], Pl[2], Pl[3], plo + asw(mrow, kb, lane));
                ldsm4(Pl[4], Pl[5], Pl[6], Pl[7], plo + asw(mrow + 16, kb, lane));
                ldsm2(W[0], W[1], whi + bsw(0, kb, lane & 15));
                ldsm2(W[2], W[3], wlo + bsw(0, kb, lane & 15));
                mma16816(accP[0], Ph,     W);
                mma16816(accP[1], Ph + 4, W);
                mma16816(accP[0], Pl,     W);
                mma16816(accP[1], Pl + 4, W);
                mma16816(accP[0], Ph,     W + 2);
                mma16816(accP[1], Ph + 4, W + 2);
            }
        }
    }

    // ---- norm reduction over 8-lane row groups ----
    #pragma unroll
    for (int i = 0; i < 4; ++i) {
        float a = sqC[i], b = sqE[i];
        #pragma unroll
        for (int off = 1; off < 8; off <<= 1) {
            a += __shfl_xor_sync(0xffffffffu, a, off);
            b += __shfl_xor_sync(0xffffffffu, b, off);
        }
        if (cq == 0) {
            const int row = cr + 32 * i;
            icn[row] = rsqrtf(a);
            ien[row] = rsqrtf(b);
        }
    }
    __syncthreads();   // all tile/staging reads done; norms visible; aliasing safe

    // ---- argmax: (value, lower-index-wins) == first-occurrence semantics ----
    float iev[16];
    #pragma unroll
    for (int nt = 0; nt < 8; ++nt) {
        iev[nt*2]     = ien[ncol + nt * 8 + 2 * t];
        iev[nt*2 + 1] = ien[ncol + nt * 8 + 2 * t + 1];
    }
    float2* red = (float2*)(smem + O_RED);
    const int slot = nw * 4 + t;
    #pragma unroll
    for (int h = 0; h < 4; ++h) {
        const int mt = h >> 1, up = h & 1;
        const int row = mrow + mt * 16 + up * 8 + g;
        float best = -3.402823466e38f;
        int   bi = 1 << 30;
        #pragma unroll
        for (int nt = 0; nt < 8; ++nt) {
            const float v0 = accD[mt][nt][up * 2]     * iev[nt*2];
            const float v1 = accD[mt][nt][up * 2 + 1] * iev[nt*2 + 1];
            const int c0 = ncol + nt * 8 + 2 * t;
            if (v0 > best || (v0 == best && c0 < bi)) { best = v0; bi = c0; }
            if (v1 > best || (v1 == best && c0 + 1 < bi)) { best = v1; bi = c0 + 1; }
        }
        red[row * 8 + slot] = make_float2(best, __int_as_float(bi));
    }

    // ---- write scaled p_c / p_e ----
    {
        float* dst = (wid < 4) ? (float*)(smem + O_PCS) : (float*)(smem + O_PES);
        const float* inv = (wid < 4) ? icn : ien;
        const int j0 = 2 * t, j1 = 2 * t + 1;
        #pragma unroll
        for (int mt = 0; mt < 2; ++mt) {
            const int r0 = mrow + mt * 16 + g, r1 = r0 + 8;
            if (j0 < 5) {
                dst[r0 * 8 + j0] = accP[mt][0] * inv[r0];
                dst[r1 * 8 + j0] = accP[mt][2] * inv[r1];
            }
            if (j1 < 5) {
                dst[r0 * 8 + j1] = accP[mt][1] * inv[r0];
                dst[r1 * 8 + j1] = accP[mt][3] * inv[r1];
            }
        }
    }
    __syncthreads();

    // ---- per-row MLP + block sum ----
    const float* pcs = (const float*)(smem + O_PCS);
    const float* pes = (const float*)(smem + O_PES);
    float partial = 0.f;
    if (tid < 128) {
        const int l = tid;
        float best = -3.402823466e38f;
        int   bi = 1 << 30;
        #pragma unroll
        for (int s2 = 0; s2 < 8; ++s2) {
            const float2 v = red[l * 8 + s2];
            const int cc = __float_as_int(v.y);
            if (v.x > best || (v.x == best && cc < bi)) { best = v.x; bi = cc; }
        }
        float h0[5];
        #pragma unroll
        for (int j = 0; j < 5; ++j)
            h0[j] = tanhf(pcs[l * 8 + j] + pes[bi * 8 + j] + __ldg(b0 + j));
        float s0 = __ldg(b1 + 0), s1 = __ldg(b1 + 1);
        #pragma unroll
        for (int j = 0; j < 5; ++j) {
            s0 += __ldg(w1 + j)     * h0[j];
            s1 += __ldg(w1 + 5 + j) * h0[j];
        }
        float h10 = tanhf(s0), h11 = tanhf(s1);
        float z = tanhf(__ldg(w2) * h10 + __ldg(w2 + 1) * h11 + __ldg(b2));
        z = tanhf(__ldg(w3) * z + __ldg(b3));
        z = tanhf(__ldg(w4) * z + __ldg(b4));
        z = tanhf(__ldg(w5) * z + __ldg(b5));
        partial = __ldg(w6) * z + __ldg(b6);
    }
    #pragma unroll
    for (int off = 16; off; off >>= 1)
        partial += __shfl_xor_sync(0xffffffffu, partial, off);
    if (lane == 0) ssum[wid] = partial;
    __syncthreads();
    if (tid == 0) {
        float tot = 0.f;
        #pragma unroll
        for (int w = 0; w < 8; ++w) tot += ssum[w];
        out[p] = tot;
    }
}

extern "C" void kernel_launch(void* const* d_in, const int* in_sizes, int n_in,
                              void* d_out, int out_size)
{
    const float* ctx = (const float*)d_in[0];
    const float* w0 = (const float*)d_in[1];  const float* b0 = (const float*)d_in[2];
    const float* w1 = (const float*)d_in[3];  const float* b1 = (const float*)d_in[4];
    const float* w2 = (const float*)d_in[5];  const float* b2 = (const float*)d_in[6];
    const float* w3 = (const float*)d_in[7];  const float* b3 = (const float*)d_in[8];
    const float* w4 = (const float*)d_in[9];  const float* b4 = (const float*)d_in[10];
    const float* w5 = (const float*)d_in[11]; const float* b5 = (const float*)d_in[12];
    const float* w6 = (const float*)d_in[13]; const float* b6 = (const float*)d_in[14];
    float* out = (float*)d_out;

    cudaFuncSetAttribute(som_mma_kernel,
                         cudaFuncAttributeMaxDynamicSharedMemorySize, SMEM_BYTES);
    som_mma_kernel<<<1024, THREADS, SMEM_BYTES>>>(
        ctx, w0, b0, w1, b1, w2, b2, w3, b3, w4, b4, w5, b5, w6, b6, out);
}

// round 13
// speedup vs baseline: 3.7656x; 1.0165x over previous
#include <cuda_runtime.h>
#include <math.h>

#define THREADS 256
#define NCH 24            // 768 / 32
#define EDIM 768

// ---- staging (single buffer) ----
#define ST_C 0            // fp32 C: 128 x 128B = 16KB
#define ST_E 16384        // fp32 E: 16KB
#define ST_W 32768        // fp32 w0: 10 rows x 128B
// ---- double-buffered bf16 tiles (offsets relative to buffer base) ----
#define TA_HI 0           // 128 x 32 bf16, 64B rows, SW64 = 8KB
#define TA_LO 8192
#define TB_HI 16384
#define TB_LO 24576
#define TWC_HI 32768      // 8 x 32 bf16 = 512B (rows 5..7 zero)
#define TWC_LO 33280
#define TWE_HI 33792
#define TWE_LO 34304
#define TBUF_SZ 34816
#define T0_OFF 34816
#define T1_OFF 69632
// ---- misc ----
#define O_ICN 104448
#define O_IEN 104960
#define O_SSUM 105472
#define SMEM_BYTES 105504
// aliases in staging region (used after GEMM completes)
#define O_RED 0           // float2[128][8]
#define O_PCS 16384
#define O_PES 24576

#define SW64(o) ((o) ^ (((o) >> 3) & 0x30u))

static __device__ __forceinline__ unsigned smem_u32(const void* p) {
    unsigned a;
    asm("{ .reg .u64 t; cvta.to.shared.u64 t, %1; cvt.u32.u64 %0, t; }" : "=r"(a) : "l"(p));
    return a;
}
static __device__ __forceinline__ void cp16(unsigned dst, const void* src) {
    asm volatile("cp.async.cg.shared.global [%0], [%1], 16;" :: "r"(dst), "l"(src));
}
static __device__ __forceinline__ void cp_commit() {
    asm volatile("cp.async.commit_group;" ::: "memory");
}
static __device__ __forceinline__ void cp_wait0() {
    asm volatile("cp.async.wait_group 0;" ::: "memory");
}
static __device__ __forceinline__ void ldsm4(unsigned& r0, unsigned& r1, unsigned& r2, unsigned& r3,
                                             unsigned a) {
    asm volatile("ldmatrix.sync.aligned.m8n8.x4.shared.b16 {%0,%1,%2,%3}, [%4];"
                 : "=r"(r0), "=r"(r1), "=r"(r2), "=r"(r3) : "r"(a));
}
static __device__ __forceinline__ void ldsm2(unsigned& r0, unsigned& r1, unsigned a) {
    asm volatile("ldmatrix.sync.aligned.m8n8.x2.shared.b16 {%0,%1}, [%2];"
                 : "=r"(r0), "=r"(r1) : "r"(a));
}
static __device__ __forceinline__ void mma16816(float* c, const unsigned* a, const unsigned* b) {
    asm volatile("mma.sync.aligned.m16n8k16.row.col.f32.bf16.bf16.f32 "
                 "{%0,%1,%2,%3}, {%4,%5,%6,%7}, {%8,%9}, {%0,%1,%2,%3};"
                 : "+f"(c[0]), "+f"(c[1]), "+f"(c[2]), "+f"(c[3])
                 : "r"(a[0]), "r"(a[1]), "r"(a[2]), "r"(a[3]), "r"(b[0]), "r"(b[1]));
}
// A-operand (m16k16 row-major) ldmatrix address, 64B rows, SW64 (tile-relative)
static __device__ __forceinline__ unsigned asw(int row0, int kb, int lane) {
    const int m = lane >> 3, r = lane & 7;
    const int row = row0 + ((m & 1) << 3) + r;
    const int byte = kb + ((m >> 1) << 4);
    return SW64((unsigned)(row * 64 + byte));
}
// B-operand ldmatrix address
static __device__ __forceinline__ unsigned bsw(int n0, int kb, int lane) {
    const int m = lane >> 3, r = lane & 7;
    const int row = n0 + ((m >> 1) << 3) + r;
    const int byte = kb + ((m & 1) << 4);
    return SW64((unsigned)(row * 64 + byte));
}
// fp32x4 -> hi bf16x4 + residual-lo bf16x4, accumulate sum of squares
static __device__ __forceinline__ void cvt_store(char* hip, char* lop, float4 v, float& sq) {
    sq += v.x * v.x + v.y * v.y + v.z * v.z + v.w * v.w;
    unsigned h01, h23, l01, l23;
    asm("cvt.rn.bf16x2.f32 %0, %2, %1;" : "=r"(h01) : "f"(v.x), "f"(v.y));
    asm("cvt.rn.bf16x2.f32 %0, %2, %1;" : "=r"(h23) : "f"(v.z), "f"(v.w));
    float f0 = __uint_as_float(h01 << 16);
    float f1 = __uint_as_float(h01 & 0xffff0000u);
    float f2 = __uint_as_float(h23 << 16);
    float f3 = __uint_as_float(h23 & 0xffff0000u);
    float r0 = v.x - f0, r1 = v.y - f1, r2 = v.z - f2, r3 = v.w - f3;
    asm("cvt.rn.bf16x2.f32 %0, %2, %1;" : "=r"(l01) : "f"(r0), "f"(r1));
    asm("cvt.rn.bf16x2.f32 %0, %2, %1;" : "=r"(l23) : "f"(r2), "f"(r3));
    *(uint2*)hip = make_uint2(h01, h23);
    *(uint2*)lop = make_uint2(l01, l23);
}

// stage one K=32 chunk (C, E, w0) gmem -> smem staging via cp.async
static __device__ __forceinline__ void stage_chunk(unsigned sb, const float* Cb, const float* Eb,
                                                   const float* w0, int cb, int tid) {
    #pragma unroll
    for (int j = 0; j < 4; ++j) {
        const int o = tid + 256 * j;                 // 0..1023
        const int row = o >> 3, q = o & 7;
        cp16(sb + ST_C + o * 16, Cb + row * EDIM + cb + q * 4);
        cp16(sb + ST_E + o * 16, Eb + row * EDIM + cb + q * 4);
    }
    if (tid < 80) {
        const int r = tid >> 3, q = tid & 7;         // 5 c-rows then 5 e-rows
        cp16(sb + ST_W + tid * 16, w0 + (r % 5) * 1536 + (r / 5) * 768 + cb + q * 4);
    }
    cp_commit();
}

// convert staged fp32 chunk into bf16 hi/lo tiles at tb_off, accumulating norms
static __device__ __forceinline__ void convert_chunk(char* smem, int tb_off, int cr, int cq,
                                                     int tid, float* sqC, float* sqE) {
    char* T = smem + tb_off;
    #pragma unroll
    for (int i = 0; i < 4; ++i) {
        const int row = cr + 32 * i;
        const int qq = (cq + row) & 7;               // quad rotation: conflict-free LDS
        float4 cv = *(const float4*)(smem + ST_C + row * 128 + qq * 16);
        float4 ev = *(const float4*)(smem + ST_E + row * 128 + qq * 16);
        const unsigned o = SW64((unsigned)(row * 64 + qq * 8));
        cvt_store(T + TA_HI + o, T + TA_LO + o, cv, sqC[i]);
        cvt_store(T + TB_HI + o, T + TB_LO + o, ev, sqE[i]);
    }
    if (tid < 80) {
        const int r = tid >> 3, q = tid & 7;
        float4 wv = *(const float4*)(smem + ST_W + tid * 16);
        const int half = r / 5, rr = r % 5;
        char* hb = T + (half ? TWE_HI : TWC_HI);
        float dmy = 0.f;
        const unsigned o = SW64((unsigned)(rr * 64 + q * 8));
        cvt_store(hb + o, hb + 512 + o, wv, dmy);
    }
}

// one k16 step (s) of the 3-split main GEMM
static __device__ __forceinline__ void gemm_main_s(float accD[2][8][4], unsigned tb, int kb,
                                                   int mrow, int ncol, int lane) {
    unsigned Ah[8], Ax[8], Bf[16];
    ldsm4(Ah[0], Ah[1], Ah[2], Ah[3], tb + TA_HI + asw(mrow, kb, lane));
    ldsm4(Ah[4], Ah[5], Ah[6], Ah[7], tb + TA_HI + asw(mrow + 16, kb, lane));
    #pragma unroll
    for (int pq = 0; pq < 4; ++pq)
        ldsm4(Bf[4*pq], Bf[4*pq+1], Bf[4*pq+2], Bf[4*pq+3],
              tb + TB_HI + bsw(ncol + 16 * pq, kb, lane));
    #pragma unroll
    for (int mt = 0; mt < 2; ++mt)
        #pragma unroll
        for (int nt = 0; nt < 8; ++nt)
            mma16816(accD[mt][nt], Ah + 4 * mt, Bf + (nt >> 1) * 4 + (nt & 1) * 2);
    ldsm4(Ax[0], Ax[1], Ax[2], Ax[3], tb + TA_LO + asw(mrow, kb, lane));
    ldsm4(Ax[4], Ax[5], Ax[6], Ax[7], tb + TA_LO + asw(mrow + 16, kb, lane));
    #pragma unroll
    for (int mt = 0; mt < 2; ++mt)
        #pragma unroll
        for (int nt = 0; nt < 8; ++nt)
            mma16816(accD[mt][nt], Ax + 4 * mt, Bf + (nt >> 1) * 4 + (nt & 1) * 2);
    #pragma unroll
    for (int pq = 0; pq < 4; ++pq)
        ldsm4(Bf[4*pq], Bf[4*pq+1], Bf[4*pq+2], Bf[4*pq+3],
              tb + TB_LO + bsw(ncol + 16 * pq, kb, lane));
    #pragma unroll
    for (int mt = 0; mt < 2; ++mt)
        #pragma unroll
        for (int nt = 0; nt < 8; ++nt)
            mma16816(accD[mt][nt], Ah + 4 * mt, Bf + (nt >> 1) * 4 + (nt & 1) * 2);
}

// w0 projection for both k16 steps (warps 0-3: p_c from A; 4-7: p_e from B)
static __device__ __forceinline__ void gemm_proj(float accP[2][4], unsigned tb, int mrow,
                                                 int isC, int lane) {
    const unsigned phi = tb + (isC ? TA_HI : TB_HI);
    const unsigned plo = phi + 8192;
    const unsigned whi = tb + (isC ? TWC_HI : TWE_HI);
    const unsigned wlo = whi + 512;
    #pragma unroll
    for (int s = 0; s < 2; ++s) {
        const int kb = s * 32;
        unsigned Ph[8], Pl[8], W[4];
        ldsm4(Ph[0], Ph[1], Ph[2], Ph[3], phi + asw(mrow, kb, lane));
        ldsm4(Ph[4], Ph[5], Ph[6], Ph[7], phi + asw(mrow + 16, kb, lane));
        ldsm4(Pl[0], Pl[1], Pl[2], Pl[3], plo + asw(mrow, kb, lane));
        ldsm4(Pl[4], Pl[5], Pl[6], Pl[7], plo + asw(mrow + 16, kb, lane));
        ldsm2(W[0], W[1], whi + bsw(0, kb, lane & 15));
        ldsm2(W[2], W[3], wlo + bsw(0, kb, lane & 15));
        mma16816(accP[0], Ph,     W);
        mma16816(accP[1], Ph + 4, W);
        mma16816(accP[0], Pl,     W);
        mma16816(accP[1], Pl + 4, W);
        mma16816(accP[0], Ph,     W + 2);
        mma16816(accP[1], Ph + 4, W + 2);
    }
}

__global__ __launch_bounds__(THREADS, 2)
void som_mma_kernel(const float* __restrict__ ctx,
                    const float* __restrict__ w0, const float* __restrict__ b0,
                    const float* __restrict__ w1, const float* __restrict__ b1,
                    const float* __restrict__ w2, const float* __restrict__ b2,
                    const float* __restrict__ w3, const float* __restrict__ b3,
                    const float* __restrict__ w4, const float* __restrict__ b4,
                    const float* __restrict__ w5, const float* __restrict__ b5,
                    const float* __restrict__ w6, const float* __restrict__ b6,
                    float* __restrict__ out)
{
    extern __shared__ char smem[];
    const unsigned sb = smem_u32(smem);
    float* icn  = (float*)(smem + O_ICN);
    float* ien  = (float*)(smem + O_IEN);
    float* ssum = (float*)(smem + O_SSUM);

    const int tid  = threadIdx.x;
    const int lane = tid & 31;
    const int wid  = tid >> 5;
    const int p    = blockIdx.x;

    const float* Cb = ctx + (size_t)p * (2 * 128 * EDIM);
    const float* Eb = Cb + 128 * EDIM;

    // zero w0 tile pads in BOTH tile buffers (rows 5..7 never written again)
    {
        const int half = tid >> 7, r = tid & 127;    // 2 x 2KB regions
        *(uint4*)(smem + (half ? T1_OFF : T0_OFF) + TWC_HI + r * 16) =
            make_uint4(0u, 0u, 0u, 0u);
    }

    const int cr = tid >> 3, cq = tid & 7;
    const int mw = wid & 3, nw = wid >> 2;
    const int mrow = mw * 32, ncol = nw * 64;
    const int g = lane >> 2, t = lane & 3;

    float accD[2][8][4];
    float accP[2][4];
    #pragma unroll
    for (int mt = 0; mt < 2; ++mt) {
        #pragma unroll
        for (int nt = 0; nt < 8; ++nt)
            #pragma unroll
            for (int k = 0; k < 4; ++k) accD[mt][nt][k] = 0.f;
        #pragma unroll
        for (int k = 0; k < 4; ++k) accP[mt][k] = 0.f;
    }
    float sqC[4] = {0.f, 0.f, 0.f, 0.f};
    float sqE[4] = {0.f, 0.f, 0.f, 0.f};

    // ---- prologue: stage + convert chunk 0, stage chunk 1 ----
    stage_chunk(sb, Cb, Eb, w0, 0, tid);
    cp_wait0();
    __syncthreads();                       // staging visible (also covers pad zeroing)
    convert_chunk(smem, T0_OFF, cr, cq, tid, sqC, sqE);
    __syncthreads();                       // staging drained
    stage_chunk(sb, Cb, Eb, w0, 32, tid);

    for (int c = 0; c < NCH; ++c) {
        const unsigned tb = sb + ((c & 1) ? T1_OFF : T0_OFF);
        const int nb_off = ((c + 1) & 1) ? T1_OFF : T0_OFF;

        if (c + 1 < NCH) cp_wait0();
        __syncthreads();   // staging[c+1] visible; prev iter's tile reads ordered

        // convert(c+1) flows straight into GEMM(c) s=0 — no barrier between
        if (c + 1 < NCH) convert_chunk(smem, nb_off, cr, cq, tid, sqC, sqE);
        gemm_main_s(accD, tb, 0, mrow, ncol, lane);

        __syncthreads();   // staging drained by convert
        if (c + 2 < NCH) stage_chunk(sb, Cb, Eb, w0, (c + 2) * 32, tid);

        gemm_main_s(accD, tb, 32, mrow, ncol, lane);
        gemm_proj(accP, tb, mrow, (wid < 4) ? 1 : 0, lane);
    }

    // ---- norm reduction over 8-lane row groups ----
    #pragma unroll
    for (int i = 0; i < 4; ++i) {
        float a = sqC[i], b = sqE[i];
        #pragma unroll
        for (int off = 1; off < 8; off <<= 1) {
            a += __shfl_xor_sync(0xffffffffu, a, off);
            b += __shfl_xor_sync(0xffffffffu, b, off);
        }
        if (cq == 0) {
            const int row = cr + 32 * i;
            icn[row] = rsqrtf(a);
            ien[row] = rsqrtf(b);
        }
    }
    __syncthreads();   // all tile/staging reads done; norms visible; aliasing safe

    // ---- argmax: (value, lower-index-wins) == first-occurrence semantics ----
    float iev[16];
    #pragma unroll
    for (int nt = 0; nt < 8; ++nt) {
        iev[nt*2]     = ien[ncol + nt * 8 + 2 * t];
        iev[nt*2 + 1] = ien[ncol + nt * 8 + 2 * t + 1];
    }
    float2* red = (float2*)(smem + O_RED);
    const int slot = nw * 4 + t;
    #pragma unroll
    for (int h = 0; h < 4; ++h) {
        const int mt = h >> 1, up = h & 1;
        const int row = mrow + mt * 16 + up * 8 + g;
        float best = -3.402823466e38f;
        int   bi = 1 << 30;
        #pragma unroll
        for (int nt = 0; nt < 8; ++nt) {
            const float v0 = accD[mt][nt][up * 2]     * iev[nt*2];
            const float v1 = accD[mt][nt][up * 2 + 1] * iev[nt*2 + 1];
            const int c0 = ncol + nt * 8 + 2 * t;
            if (v0 > best || (v0 == best && c0 < bi)) { best = v0; bi = c0; }
            if (v1 > best || (v1 == best && c0 + 1 < bi)) { best = v1; bi = c0 + 1; }
        }
        red[row * 8 + slot] = make_float2(best, __int_as_float(bi));
    }

    // ---- write scaled p_c / p_e ----
    {
        float* dst = (wid < 4) ? (float*)(smem + O_PCS) : (float*)(smem + O_PES);
        const float* inv = (wid < 4) ? icn : ien;
        const int j0 = 2 * t, j1 = 2 * t + 1;
        #pragma unroll
        for (int mt = 0; mt < 2; ++mt) {
            const int r0 = mrow + mt * 16 + g, r1 = r0 + 8;
            if (j0 < 5) {
                dst[r0 * 8 + j0] = accP[mt][0] * inv[r0];
                dst[r1 * 8 + j0] = accP[mt][2] * inv[r1];
            }
            if (j1 < 5) {
                dst[r0 * 8 + j1] = accP[mt][1] * inv[r0];
                dst[r1 * 8 + j1] = accP[mt][3] * inv[r1];
            }
        }
    }
    __syncthreads();

    // ---- per-row MLP + block sum ----
    const float* pcs = (const float*)(smem + O_PCS);
    const float* pes = (const float*)(smem + O_PES);
    float partial = 0.f;
    if (tid < 128) {
        const int l = tid;
        float best = -3.402823466e38f;
        int   bi = 1 << 30;
        #pragma unroll
        for (int s2 = 0; s2 < 8; ++s2) {
            const float2 v = red[l * 8 + s2];
            const int cc = __float_as_int(v.y);
            if (v.x > best || (v.x == best && cc < bi)) { best = v.x; bi = cc; }
        }
        float h0[5];
        #pragma unroll
        for (int j = 0; j < 5; ++j)
            h0[j] = tanhf(pcs[l * 8 + j] + pes[bi * 8 + j] + __ldg(b0 + j));
        float s0 = __ldg(b1 + 0), s1 = __ldg(b1 + 1);
        #pragma unroll
        for (int j = 0; j < 5; ++j) {
            s0 += __ldg(w1 + j)     * h0[j];
            s1 += __ldg(w1 + 5 + j) * h0[j];
        }
        float h10 = tanhf(s0), h11 = tanhf(s1);
        float z = tanhf(__ldg(w2) * h10 + __ldg(w2 + 1) * h11 + __ldg(b2));
        z = tanhf(__ldg(w3) * z + __ldg(b3));
        z = tanhf(__ldg(w4) * z + __ldg(b4));
        z = tanhf(__ldg(w5) * z + __ldg(b5));
        partial = __ldg(w6) * z + __ldg(b6);
    }
    #pragma unroll
    for (int off = 16; off; off >>= 1)
        partial += __shfl_xor_sync(0xffffffffu, partial, off);
    if (lane == 0) ssum[wid] = partial;
    __syncthreads();
    if (tid == 0) {
        float tot = 0.f;
        #pragma unroll
        for (int w = 0; w < 8; ++w) tot += ssum[w];
        out[p] = tot;
    }
}

extern "C" void kernel_launch(void* const* d_in, const int* in_sizes, int n_in,
                              void* d_out, int out_size)
{
    const float* ctx = (const float*)d_in[0];
    const float* w0 = (const float*)d_in[1];  const float* b0 = (const float*)d_in[2];
    const float* w1 = (const float*)d_in[3];  const float* b1 = (const float*)d_in[4];
    const float* w2 = (const float*)d_in[5];  const float* b2 = (const float*)d_in[6];
    const float* w3 = (const float*)d_in[7];  const float* b3 = (const float*)d_in[8];
    const float* w4 = (const float*)d_in[9];  const float* b4 = (const float*)d_in[10];
    const float* w5 = (const float*)d_in[11]; const float* b5 = (const float*)d_in[12];
    const float* w6 = (const float*)d_in[13]; const float* b6 = (const float*)d_in[14];
    float* out = (float*)d_out;

    cudaFuncSetAttribute(som_mma_kernel,
                         cudaFuncAttributeMaxDynamicSharedMemorySize, SMEM_BYTES);
    som_mma_kernel<<<1024, THREADS, SMEM_BYTES>>>(
        ctx, w0, b0, w1, b1, w2, b2, w3, b3, w4, b4, w5, b5, w6, b6, out);
}

// round 16
// speedup vs baseline: 3.9233x; 1.0419x over previous
#include <cuda_runtime.h>
#include <math.h>

#define THREADS 256
#define NCH 24            // 768 / 32
#define EDIM 768

// ---- double-buffered fp32 staging ----
#define S0_C 0            // fp32 C: 128 x 128B = 16KB
#define S0_E 16384
#define S0_W 32768        // fp32 w0: 10 rows x 128B = 1280B
#define S1_OFF 34816
// ---- single bf16 tile buffer (offsets relative to T_OFF) ----
#define T_OFF 69632
#define TA_HI 0           // 128 x 32 bf16, 64B rows, SW64 = 8KB
#define TA_LO 8192
#define TB_HI 16384
#define TB_LO 24576
#define TWC_HI 32768      // 8 x 32 bf16 = 512B (rows 5..7 zero)
#define TWC_LO 33280
#define TWE_HI 33792
#define TWE_LO 34304
// ---- misc ----
#define O_ICN 104448
#define O_IEN 104960
#define O_SSUM 105472
#define SMEM_BYTES 105504
// aliases in staging region (used after GEMM completes)
#define O_RED 0           // float2[128][8]
#define O_PCS 16384
#define O_PES 24576

#define SW64(o) ((o) ^ (((o) >> 3) & 0x30u))

static __device__ __forceinline__ unsigned smem_u32(const void* p) {
    unsigned a;
    asm("{ .reg .u64 t; cvta.to.shared.u64 t, %1; cvt.u32.u64 %0, t; }" : "=r"(a) : "l"(p));
    return a;
}
static __device__ __forceinline__ void cp16(unsigned dst, const void* src) {
    asm volatile("cp.async.cg.shared.global [%0], [%1], 16;" :: "r"(dst), "l"(src));
}
static __device__ __forceinline__ void cp_commit() {
    asm volatile("cp.async.commit_group;" ::: "memory");
}
static __device__ __forceinline__ void cp_wait0() {
    asm volatile("cp.async.wait_group 0;" ::: "memory");
}
static __device__ __forceinline__ void cp_wait1() {
    asm volatile("cp.async.wait_group 1;" ::: "memory");
}
static __device__ __forceinline__ void ldsm4(unsigned& r0, unsigned& r1, unsigned& r2, unsigned& r3,
                                             unsigned a) {
    asm volatile("ldmatrix.sync.aligned.m8n8.x4.shared.b16 {%0,%1,%2,%3}, [%4];"
                 : "=r"(r0), "=r"(r1), "=r"(r2), "=r"(r3) : "r"(a));
}
static __device__ __forceinline__ void ldsm2(unsigned& r0, unsigned& r1, unsigned a) {
    asm volatile("ldmatrix.sync.aligned.m8n8.x2.shared.b16 {%0,%1}, [%2];"
                 : "=r"(r0), "=r"(r1) : "r"(a));
}
static __device__ __forceinline__ void mma16816(float* c, const unsigned* a, const unsigned* b) {
    asm volatile("mma.sync.aligned.m16n8k16.row.col.f32.bf16.bf16.f32 "
                 "{%0,%1,%2,%3}, {%4,%5,%6,%7}, {%8,%9}, {%0,%1,%2,%3};"
                 : "+f"(c[0]), "+f"(c[1]), "+f"(c[2]), "+f"(c[3])
                 : "r"(a[0]), "r"(a[1]), "r"(a[2]), "r"(a[3]), "r"(b[0]), "r"(b[1]));
}
// A-operand (m16k16 row-major) ldmatrix address, 64B rows, SW64 (tile-relative)
static __device__ __forceinline__ unsigned asw(int row0, int kb, int lane) {
    const int m = lane >> 3, r = lane & 7;
    const int row = row0 + ((m & 1) << 3) + r;
    const int byte = kb + ((m >> 1) << 4);
    return SW64((unsigned)(row * 64 + byte));
}
// B-operand ldmatrix address
static __device__ __forceinline__ unsigned bsw(int n0, int kb, int lane) {
    const int m = lane >> 3, r = lane & 7;
    const int row = n0 + ((m >> 1) << 3) + r;
    const int byte = kb + ((m & 1) << 4);
    return SW64((unsigned)(row * 64 + byte));
}
// fp32x4 -> hi bf16x4 + residual-lo bf16x4, accumulate sum of squares
static __device__ __forceinline__ void cvt_store(char* hip, char* lop, float4 v, float& sq) {
    sq += v.x * v.x + v.y * v.y + v.z * v.z + v.w * v.w;
    unsigned h01, h23, l01, l23;
    asm("cvt.rn.bf16x2.f32 %0, %2, %1;" : "=r"(h01) : "f"(v.x), "f"(v.y));
    asm("cvt.rn.bf16x2.f32 %0, %2, %1;" : "=r"(h23) : "f"(v.z), "f"(v.w));
    float f0 = __uint_as_float(h01 << 16);
    float f1 = __uint_as_float(h01 & 0xffff0000u);
    float f2 = __uint_as_float(h23 << 16);
    float f3 = __uint_as_float(h23 & 0xffff0000u);
    float r0 = v.x - f0, r1 = v.y - f1, r2 = v.z - f2, r3 = v.w - f3;
    asm("cvt.rn.bf16x2.f32 %0, %2, %1;" : "=r"(l01) : "f"(r0), "f"(r1));
    asm("cvt.rn.bf16x2.f32 %0, %2, %1;" : "=r"(l23) : "f"(r2), "f"(r3));
    *(uint2*)hip = make_uint2(h01, h23);
    *(uint2*)lop = make_uint2(l01, l23);
}

// stage one K=32 chunk (C, E, w0) into staging buffer at st_off
static __device__ __forceinline__ void stage_chunk(unsigned sb, int st_off, const float* Cb,
                                                   const float* Eb, const float* w0,
                                                   int cb, int tid) {
    #pragma unroll
    for (int j = 0; j < 4; ++j) {
        const int o = tid + 256 * j;                 // 0..1023
        const int row = o >> 3, q = o & 7;
        cp16(sb + st_off + S0_C + o * 16, Cb + row * EDIM + cb + q * 4);
        cp16(sb + st_off + S0_E + o * 16, Eb + row * EDIM + cb + q * 4);
    }
    if (tid < 80) {
        const int r = tid >> 3, q = tid & 7;         // 5 c-rows then 5 e-rows
        cp16(sb + st_off + S0_W + tid * 16, w0 + (r % 5) * 1536 + (r / 5) * 768 + cb + q * 4);
    }
    cp_commit();
}

// convert staged fp32 chunk (at st_off) into the bf16 tile buffer, accumulating norms
static __device__ __forceinline__ void convert_chunk(char* smem, int st_off, int cr, int cq,
                                                     int tid, float* sqC, float* sqE) {
    char* T = smem + T_OFF;
    #pragma unroll
    for (int i = 0; i < 4; ++i) {
        const int row = cr + 32 * i;
        const int qq = (cq + row) & 7;               // quad rotation: conflict-free LDS
        float4 cv = *(const float4*)(smem + st_off + S0_C + row * 128 + qq * 16);
        float4 ev = *(const float4*)(smem + st_off + S0_E + row * 128 + qq * 16);
        const unsigned o = SW64((unsigned)(row * 64 + qq * 8));
        cvt_store(T + TA_HI + o, T + TA_LO + o, cv, sqC[i]);
        cvt_store(T + TB_HI + o, T + TB_LO + o, ev, sqE[i]);
    }
    if (tid < 80) {
        const int r = tid >> 3, q = tid & 7;
        float4 wv = *(const float4*)(smem + st_off + S0_W + tid * 16);
        const int half = r / 5, rr = r % 5;
        char* hb = T + (half ? TWE_HI : TWC_HI);
        float dmy = 0.f;
        const unsigned o = SW64((unsigned)(rr * 64 + q * 8));
        cvt_store(hb + o, hb + 512 + o, wv, dmy);
    }
}

// one k16 step (kb) of the 3-split main GEMM
static __device__ __forceinline__ void gemm_main_s(float accD[2][8][4], unsigned tb, int kb,
                                                   int mrow, int ncol, int lane) {
    unsigned Ah[8], Ax[8], Bf[16];
    ldsm4(Ah[0], Ah[1], Ah[2], Ah[3], tb + TA_HI + asw(mrow, kb, lane));
    ldsm4(Ah[4], Ah[5], Ah[6], Ah[7], tb + TA_HI + asw(mrow + 16, kb, lane));
    #pragma unroll
    for (int pq = 0; pq < 4; ++pq)
        ldsm4(Bf[4*pq], Bf[4*pq+1], Bf[4*pq+2], Bf[4*pq+3],
              tb + TB_HI + bsw(ncol + 16 * pq, kb, lane));
    #pragma unroll
    for (int mt = 0; mt < 2; ++mt)
        #pragma unroll
        for (int nt = 0; nt < 8; ++nt)
            mma16816(accD[mt][nt], Ah + 4 * mt, Bf + (nt >> 1) * 4 + (nt & 1) * 2);
    ldsm4(Ax[0], Ax[1], Ax[2], Ax[3], tb + TA_LO + asw(mrow, kb, lane));
    ldsm4(Ax[4], Ax[5], Ax[6], Ax[7], tb + TA_LO + asw(mrow + 16, kb, lane));
    #pragma unroll
    for (int mt = 0; mt < 2; ++mt)
        #pragma unroll
        for (int nt = 0; nt < 8; ++nt)
            mma16816(accD[mt][nt], Ax + 4 * mt, Bf + (nt >> 1) * 4 + (nt & 1) * 2);
    #pragma unroll
    for (int pq = 0; pq < 4; ++pq)
        ldsm4(Bf[4*pq], Bf[4*pq+1], Bf[4*pq+2], Bf[4*pq+3],
              tb + TB_LO + bsw(ncol + 16 * pq, kb, lane));
    #pragma unroll
    for (int mt = 0; mt < 2; ++mt)
        #pragma unroll
        for (int nt = 0; nt < 8; ++nt)
            mma16816(accD[mt][nt], Ah + 4 * mt, Bf + (nt >> 1) * 4 + (nt & 1) * 2);
}

// w0 projection for both k16 steps (warps 0-3: p_c from A; 4-7: p_e from B)
static __device__ __forceinline__ void gemm_proj(float accP[2][4], unsigned tb, int mrow,
                                                 int isC, int lane) {
    const unsigned phi = tb + (isC ? TA_HI : TB_HI);
    const unsigned plo = phi + 8192;
    const unsigned whi = tb + (isC ? TWC_HI : TWE_HI);
    const unsigned wlo = whi + 512;
    #pragma unroll
    for (int s = 0; s < 2; ++s) {
        const int kb = s * 32;
        unsigned Ph[8], Pl[8], W[4];
        ldsm4(Ph[0], Ph[1], Ph[2], Ph[3], phi + asw(mrow, kb, lane));
        ldsm4(Ph[4], Ph[5], Ph[6], Ph[7], phi + asw(mrow + 16, kb, lane));
        ldsm4(Pl[0], Pl[1], Pl[2], Pl[3], plo + asw(mrow, kb, lane));
        ldsm4(Pl[4], Pl[5], Pl[6], Pl[7], plo + asw(mrow + 16, kb, lane));
        ldsm2(W[0], W[1], whi + bsw(0, kb, lane & 15));
        ldsm2(W[2], W[3], wlo + bsw(0, kb, lane & 15));
        mma16816(accP[0], Ph,     W);
        mma16816(accP[1], Ph + 4, W);
        mma16816(accP[0], Pl,     W);
        mma16816(accP[1], Pl + 4, W);
        mma16816(accP[0], Ph,     W + 2);
        mma16816(accP[1], Ph + 4, W + 2);
    }
}

__global__ __launch_bounds__(THREADS, 2)
void som_mma_kernel(const float* __restrict__ ctx,
                    const float* __restrict__ w0, const float* __restrict__ b0,
                    const float* __restrict__ w1, const float* __restrict__ b1,
                    const float* __restrict__ w2, const float* __restrict__ b2,
                    const float* __restrict__ w3, const float* __restrict__ b3,
                    const float* __restrict__ w4, const float* __restrict__ b4,
                    const float* __restrict__ w5, const float* __restrict__ b5,
                    const float* __restrict__ w6, const float* __restrict__ b6,
                    float* __restrict__ out)
{
    extern __shared__ char smem[];
    const unsigned sb = smem_u32(smem);
    float* icn  = (float*)(smem + O_ICN);
    float* ien  = (float*)(smem + O_IEN);
    float* ssum = (float*)(smem + O_SSUM);

    const int tid  = threadIdx.x;
    const int lane = tid & 31;
    const int wid  = tid >> 5;
    const int p    = blockIdx.x;

    const float* Cb = ctx + (size_t)p * (2 * 128 * EDIM);
    const float* Eb = Cb + 128 * EDIM;

    // zero w0 tile pads (rows 5..7 of the 4 w0 tiles; never written again)
    if (tid < 128) *(uint4*)(smem + T_OFF + TWC_HI + tid * 16) = make_uint4(0u, 0u, 0u, 0u);

    const int cr = tid >> 3, cq = tid & 7;
    const int mw = wid & 3, nw = wid >> 2;
    const int mrow = mw * 32, ncol = nw * 64;
    const int g = lane >> 2, t = lane & 3;

    float accD[2][8][4];
    float accP[2][4];
    #pragma unroll
    for (int mt = 0; mt < 2; ++mt) {
        #pragma unroll
        for (int nt = 0; nt < 8; ++nt)
            #pragma unroll
            for (int k = 0; k < 4; ++k) accD[mt][nt][k] = 0.f;
        #pragma unroll
        for (int k = 0; k < 4; ++k) accP[mt][k] = 0.f;
    }
    float sqC[4] = {0.f, 0.f, 0.f, 0.f};
    float sqE[4] = {0.f, 0.f, 0.f, 0.f};

    // ---- prologue: fill both staging buffers (groups 0 and 1 in flight) ----
    stage_chunk(sb, 0,      Cb, Eb, w0, 0,  tid);
    stage_chunk(sb, S1_OFF, Cb, Eb, w0, 32, tid);

    for (int c = 0; c < NCH; ++c) {
        const int st_off = (c & 1) ? S1_OFF : 0;

        // group c complete; group c+1 stays in flight through this whole iteration
        if (c + 1 < NCH) cp_wait1(); else cp_wait0();
        __syncthreads();   // staging[c] visible; GEMM(c-1) tile reads done

        convert_chunk(smem, st_off, cr, cq, tid, sqC, sqE);
        __syncthreads();   // tiles ready; staging[c] drained

        // refill the freed buffer immediately -> DRAM busy during GEMM below
        if (c + 2 < NCH) stage_chunk(sb, st_off, Cb, Eb, w0, (c + 2) * 32, tid);

        const unsigned tb = sb + T_OFF;
        gemm_main_s(accD, tb, 0,  mrow, ncol, lane);
        gemm_main_s(accD, tb, 32, mrow, ncol, lane);
        gemm_proj(accP, tb, mrow, (wid < 4) ? 1 : 0, lane);
    }

    // ---- norm reduction over 8-lane row groups ----
    #pragma unroll
    for (int i = 0; i < 4; ++i) {
        float a = sqC[i], b = sqE[i];
        #pragma unroll
        for (int off = 1; off < 8; off <<= 1) {
            a += __shfl_xor_sync(0xffffffffu, a, off);
            b += __shfl_xor_sync(0xffffffffu, b, off);
        }
        if (cq == 0) {
            const int row = cr + 32 * i;
            icn[row] = rsqrtf(a);
            ien[row] = rsqrtf(b);
        }
    }
    __syncthreads();   // all tile/staging reads done; norms visible; aliasing safe

    // ---- argmax: (value, lower-index-wins) == first-occurrence semantics ----
    float iev[16];
    #pragma unroll
    for (int nt = 0; nt < 8; ++nt) {
        iev[nt*2]     = ien[ncol + nt * 8 + 2 * t];
        iev[nt*2 + 1] = ien[ncol + nt * 8 + 2 * t + 1];
    }
    float2* red = (float2*)(smem + O_RED);
    const int slot = nw * 4 + t;
    #pragma unroll
    for (int h = 0; h < 4; ++h) {
        const int mt = h >> 1, up = h & 1;
        const int row = mrow + mt * 16 + up * 8 + g;
        float best = -3.402823466e38f;
        int   bi = 1 << 30;
        #pragma unroll
        for (int nt = 0; nt < 8; ++nt) {
            const float v0 = accD[mt][nt][up * 2]     * iev[nt*2];
            const float v1 = accD[mt][nt][up * 2 + 1] * iev[nt*2 + 1];
            const int c0 = ncol + nt * 8 + 2 * t;
            if (v0 > best || (v0 == best && c0 < bi)) { best = v0; bi = c0; }
            if (v1 > best || (v1 == best && c0 + 1 < bi)) { best = v1; bi = c0 + 1; }
        }
        red[row * 8 + slot] = make_float2(best, __int_as_float(bi));
    }

    // ---- write scaled p_c / p_e ----
    {
        float* dst = (wid < 4) ? (float*)(smem + O_PCS) : (float*)(smem + O_PES);
        const float* inv = (wid < 4) ? icn : ien;
        const int j0 = 2 * t, j1 = 2 * t + 1;
        #pragma unroll
        for (int mt = 0; mt < 2; ++mt) {
            const int r0 = mrow + mt * 16 + g, r1 = r0 + 8;
            if (j0 < 5) {
                dst[r0 * 8 + j0] = accP[mt][0] * inv[r0];
                dst[r1 * 8 + j0] = accP[mt][2] * inv[r1];
            }
            if (j1 < 5) {
                dst[r0 * 8 + j1] = accP[mt][1] * inv[r0];
                dst[r1 * 8 + j1] = accP[mt][3] * inv[r1];
            }
        }
    }
    __syncthreads();

    // ---- per-row MLP + block sum ----
    const float* pcs = (const float*)(smem + O_PCS);
    const float* pes = (const float*)(smem + O_PES);
    float partial = 0.f;
    if (tid < 128) {
        const int l = tid;
        float best = -3.402823466e38f;
        int   bi = 1 << 30;
        #pragma unroll
        for (int s2 = 0; s2 < 8; ++s2) {
            const float2 v = red[l * 8 + s2];
            const int cc = __float_as_int(v.y);
            if (v.x > best || (v.x == best && cc < bi)) { best = v.x; bi = cc; }
        }
        float h0[5];
        #pragma unroll
        for (int j = 0; j < 5; ++j)
            h0[j] = tanhf(pcs[l * 8 + j] + pes[bi * 8 + j] + __ldg(b0 + j));
        float s0 = __ldg(b1 + 0), s1 = __ldg(b1 + 1);
        #pragma unroll
        for (int j = 0; j < 5; ++j) {
            s0 += __ldg(w1 + j)     * h0[j];
            s1 += __ldg(w1 + 5 + j) * h0[j];
        }
        float h10 = tanhf(s0), h11 = tanhf(s1);
        float z = tanhf(__ldg(w2) * h10 + __ldg(w2 + 1) * h11 + __ldg(b2));
        z = tanhf(__ldg(w3) * z + __ldg(b3));
        z = tanhf(__ldg(w4) * z + __ldg(b4));
        z = tanhf(__ldg(w5) * z + __ldg(b5));
        partial = __ldg(w6) * z + __ldg(b6);
    }
    #pragma unroll
    for (int off = 16; off; off >>= 1)
        partial += __shfl_xor_sync(0xffffffffu, partial, off);
    if (lane == 0) ssum[wid] = partial;
    __syncthreads();
    if (tid == 0) {
        float tot = 0.f;
        #pragma unroll
        for (int w = 0; w < 8; ++w) tot += ssum[w];
        out[p] = tot;
    }
}

extern "C" void kernel_launch(void* const* d_in, const int* in_sizes, int n_in,
                              void* d_out, int out_size)
{
    const float* ctx = (const float*)d_in[0];
    const float* w0 = (const float*)d_in[1];  const float* b0 = (const float*)d_in[2];
    const float* w1 = (const float*)d_in[3];  const float* b1 = (const float*)d_in[4];
    const float* w2 = (const float*)d_in[5];  const float* b2 = (const float*)d_in[6];
    const float* w3 = (const float*)d_in[7];  const float* b3 = (const float*)d_in[8];
    const float* w4 = (const float*)d_in[9];  const float* b4 = (const float*)d_in[10];
    const float* w5 = (const float*)d_in[11]; const float* b5 = (const float*)d_in[12];
    const float* w6 = (const float*)d_in[13]; const float* b6 = (const float*)d_in[14];
    float* out = (float*)d_out;

    cudaFuncSetAttribute(som_mma_kernel,
                         cudaFuncAttributeMaxDynamicSharedMemorySize, SMEM_BYTES);
    som_mma_kernel<<<1024, THREADS, SMEM_BYTES>>>(
        ctx, w0, b0, w1, b1, w2, b2, w3, b3, w4, b4, w5, b5, w6, b6, out);
}